// round 4
// baseline (speedup 1.0000x reference)
#include <cuda_runtime.h>
#include <cstdint>

#define NIMG 8
#define NCLS 80
#define HW 40000
#define CAND_CAP 262144
#define TOPK 1000
#define OUTK 100
#define LINES_PP 1250            /* 128B lines per class plane (40000/32) */
#define LINES_PAD 1280
#define TAGS_PER_IMG (NCLS * LINES_PAD)   /* 102400 */

#define XC_TAG  (-2.9446f)       /* conservative superset of p>0.05 */
#define XC_HIST (-2.9443f)       /* conservative subset of p>0.05  */
#define CBIN    (-4.76837158203125e-7f)   /* -4 * 2^-23 */
#define BIN_MARGIN 5

// ---------------- scratch (device globals; no allocation allowed) ----------
__device__ uint32_t            g_hist[NIMG][256];
__device__ int                 g_bcm[NIMG];
__device__ int                 g_cnt[NIMG];
__device__ unsigned char       g_tag[NIMG * TAGS_PER_IMG];
__device__ unsigned long long  g_cand[NIMG][CAND_CAP];
__device__ float               g_score[NIMG][TOPK];
__device__ int                 g_label[NIMG][TOPK];
__device__ float4              g_box[NIMG][TOPK];
__device__ float4              g_obox[NIMG][TOPK];

// exact sigmoid: XLA logistic expansion 1/(1+exp(-x)), IEEE div
__device__ __forceinline__ float sigm(float x) {
    return __fdiv_rn(1.0f, __fadd_rn(1.0f, expf(-x)));
}

// cheap scaled softplus-log: ~ 2^23 * log2(1 + e^-v). No MUFU, no div.
// Identical in pass1 and collect (bit-identical binning).
__device__ __forceinline__ float slog(float v) {
    float u  = v * -1.4426950408889634f;
    u = fmaxf(u, -126.0f);
    float fi = fmaf(u, 8388608.0f, 1065353216.0f);       // Schraudolph 2^u
    float ex = __int_as_float((int)fi);
    float w  = __fadd_rn(1.0f, ex);
    return (float)(__float_as_int(w) - 1065353216);      // ~= 2^23*log2(w)
}
__device__ __forceinline__ float bval(float sx, float sy) {
    return fmaf(sx + sy, CBIN, 256.0f);
}

// ---------------------------------------------------------------------------
__global__ void k_zero() {
    int t = blockIdx.x * blockDim.x + threadIdx.x;
    if (t < NIMG * 256) ((uint32_t*)g_hist)[t] = 0;
    if (t < NIMG) g_cnt[t] = 0;
}

// ---------------------------------------------------------------------------
// Pass 1 (R2 version, unchanged): one full read of cls. Per-128B-line max bin
// -> 1-byte tag; line-level histogram for the cutoff.
__global__ void k_pass1(const float* __restrict__ cls, const float* __restrict__ cent) {
    __shared__ float    s_g[1024];
    __shared__ uint32_t s_hist[256];
    const int n = blockIdx.y, blk = blockIdx.x, tid = threadIdx.x;
    const int base = blk << 10;
    const int lim = min(1024, HW - base);

    for (int i = tid; i < 256; i += 256) s_hist[i] = 0;
    for (int i = tid; i < lim; i += 256)
        s_g[i] = slog(cent[n * HW + base + i]);
    __syncthreads();

    const float4* cls4 = (const float4*)cls;
    const int pf4 = (base >> 2) + tid;
    const bool act = pf4 < (HW / 4);
    const int gline = (blk << 5) + (tid >> 3);
    const bool lvalid = gline < LINES_PP;
    const int tagbase = n * TAGS_PER_IMG + gline;
    const int ibase = n * (NCLS * (HW / 4)) + pf4;

    float g0 = 0.f, g1 = 0.f, g2 = 0.f, g3 = 0.f;
    if (act) { g0 = s_g[tid*4]; g1 = s_g[tid*4+1]; g2 = s_g[tid*4+2]; g3 = s_g[tid*4+3]; }

    for (int c = 0; c < NCLS; ++c) {
        float tmax = -1e30f, hmax = -1e30f;
        if (act) {
            float4 v = cls4[ibase + c * (HW / 4)];
            float b0 = bval(slog(v.x), g0);
            float b1 = bval(slog(v.y), g1);
            float b2 = bval(slog(v.z), g2);
            float b3 = bval(slog(v.w), g3);
            if (v.x > XC_TAG)  tmax = fmaxf(tmax, b0);
            if (v.y > XC_TAG)  tmax = fmaxf(tmax, b1);
            if (v.z > XC_TAG)  tmax = fmaxf(tmax, b2);
            if (v.w > XC_TAG)  tmax = fmaxf(tmax, b3);
            if (v.x > XC_HIST) hmax = fmaxf(hmax, b0);
            if (v.y > XC_HIST) hmax = fmaxf(hmax, b1);
            if (v.z > XC_HIST) hmax = fmaxf(hmax, b2);
            if (v.w > XC_HIST) hmax = fmaxf(hmax, b3);
        }
        tmax = fmaxf(tmax, __shfl_xor_sync(0xffffffffu, tmax, 1));
        tmax = fmaxf(tmax, __shfl_xor_sync(0xffffffffu, tmax, 2));
        tmax = fmaxf(tmax, __shfl_xor_sync(0xffffffffu, tmax, 4));
        hmax = fmaxf(hmax, __shfl_xor_sync(0xffffffffu, hmax, 1));
        hmax = fmaxf(hmax, __shfl_xor_sync(0xffffffffu, hmax, 2));
        hmax = fmaxf(hmax, __shfl_xor_sync(0xffffffffu, hmax, 4));
        if ((tid & 7) == 0 && lvalid) {
            int tb = (int)floorf(tmax);
            tb = max(0, min(255, tb));
            g_tag[tagbase + c * LINES_PAD] = (unsigned char)tb;
            if (hmax > -1e29f) {
                int hb = max(0, min(255, (int)floorf(hmax)));
                atomicAdd(&s_hist[hb], 1u);
            }
        }
    }
    __syncthreads();
    for (int i = tid; i < 256; i += 256) {
        uint32_t v = s_hist[i];
        if (v) atomicAdd(&g_hist[n][i], v);
    }
}

// ---------------------------------------------------------------------------
// cutoff: highest bin with >=1000 lines above, minus safety margin
__global__ void k_cutoff() {
    int n = threadIdx.x;
    if (n >= NIMG) return;
    int cum[256];
    int acc = 0;
    for (int b = 255; b >= 0; --b) { acc += (int)g_hist[n][b]; cum[b] = acc; }
    int bcl = 0;
    for (int b = 255; b >= 0; --b) if (cum[b] >= TOPK) { bcl = b; break; }
    int m = bcl - BIN_MARGIN; if (m < 0) m = 0;
    while (m < bcl && 32 * cum[m] > CAND_CAP) ++m;   // capacity guard
    g_bcm[n] = m;
}

// ---------------------------------------------------------------------------
// Collect (NEW): flat warp-per-32-tag-slots scan; warp cooperatively
// processes hit lines, warp-aggregated pushes. No block-local lists.
__global__ void __launch_bounds__(256) k_collect(const float* __restrict__ cls,
                                                 const float* __restrict__ cent) {
    const int n = blockIdx.y, tid = threadIdx.x;
    const int lane = tid & 31;
    const int wg = blockIdx.x * 8 + (tid >> 5);          // 0..3199
    const int slot = wg * 32 + lane;                     // < TAGS_PER_IMG
    const int bcm = g_bcm[n];
    const float fb = (float)bcm;

    bool hit = false;
    {
        int l32 = slot % LINES_PAD;
        if (l32 < LINES_PP && (int)g_tag[n * TAGS_PER_IMG + slot] >= bcm) hit = true;
    }
    unsigned hm = __ballot_sync(0xffffffffu, hit);

    while (hm) {
        int src = __ffs(hm) - 1; hm &= hm - 1;
        int hslot = wg * 32 + src;
        int c = hslot / LINES_PAD, l = hslot % LINES_PAD;
        int wpos = l * 32 + lane;
        float x = cls[(n * NCLS + c) * HW + wpos];
        float y = cent[n * HW + wpos];
        bool sel = false;
        unsigned key = 0, idx = 0;
        if (x > XC_TAG) {
            float b = bval(slog(x), slog(y));            // bit-identical to pass1
            if (b >= fb) {
                float p = sigm(x);                       // exact path for survivors
                if (p > 0.05f) {
                    float sc = __fmul_rn(p, sigm(y));
                    key = __float_as_uint(sc);
                    idx = (unsigned)(wpos * NCLS + c);
                    sel = true;
                }
            }
        }
        unsigned m = __ballot_sync(0xffffffffu, sel);
        if (sel) {
            int leader = __ffs(m) - 1;
            int rank = __popc(m & ((1u << lane) - 1u));
            int basep = 0;
            if (lane == leader) basep = atomicAdd(&g_cnt[n], __popc(m));
            basep = __shfl_sync(m, basep, leader);
            int pos = basep + rank;
            if (pos < CAND_CAP)
                g_cand[n][pos] = ((unsigned long long)key << 32) | (unsigned)(~idx);
        }
    }
}

// ---------------------------------------------------------------------------
// K4: exact top-1000 per image (maxkey-based fine hist -> refine -> bitonic),
// decode boxes
__global__ void __launch_bounds__(1024) k_select(const float* __restrict__ loc2,
                                                 const float* __restrict__ reg,
                                                 const int* __restrict__ isz) {
    __shared__ uint32_t s_hist[1024];
    __shared__ uint32_t s_cum[1024];
    __shared__ unsigned long long s_buf[4096];
    __shared__ unsigned s_wmax[32];
    __shared__ int s_cnt2, s_bf, s_rb;
    const int n = blockIdx.x, tid = threadIdx.x;
    const int Mn = min(g_cnt[n], CAND_CAP);

    s_hist[tid] = 0;
    if (tid == 0) { s_cnt2 = 0; s_bf = 0; }

    unsigned mk = 0;
    for (int i = tid; i < Mn; i += 1024) mk = max(mk, (unsigned)(g_cand[n][i] >> 32));
    for (int o = 16; o; o >>= 1) mk = max(mk, __shfl_xor_sync(0xffffffffu, mk, o));
    if ((tid & 31) == 0) s_wmax[tid >> 5] = mk;
    __syncthreads();
    if (tid == 0) {
        unsigned m2 = 0;
        for (int i = 0; i < 32; ++i) m2 = max(m2, s_wmax[i]);
        s_rb = (int)(m2 >> 17) - 1023;
    }
    __syncthreads();
    const int relbase = s_rb;

    for (int i = tid; i < Mn; i += 1024) {
        unsigned key = (unsigned)(g_cand[n][i] >> 32);
        int rel = (int)(key >> 17) - relbase;
        if (rel >= 0) atomicAdd(&s_hist[rel], 1u);
    }
    __syncthreads();

    s_cum[tid] = s_hist[tid];
    __syncthreads();
    for (int off = 1; off < 1024; off <<= 1) {
        uint32_t add = (tid + off < 1024) ? s_cum[tid + off] : 0u;
        __syncthreads();
        s_cum[tid] += add;
        __syncthreads();
    }
    const int total = (int)s_cum[0];
    const int target = min(TOPK, total);
    if (target > 0) {
        if ((int)s_cum[tid] >= target && (tid == 1023 || (int)s_cum[tid + 1] < target))
            s_bf = tid;
    }
    __syncthreads();
    const int bf = s_bf;

    for (int i = tid; i < Mn; i += 1024) {
        unsigned long long pk = g_cand[n][i];
        int rel = (int)((unsigned)(pk >> 32) >> 17) - relbase;
        if (rel >= bf) {
            int p = atomicAdd(&s_cnt2, 1);
            if (p < 4096) s_buf[p] = pk;
        }
    }
    __syncthreads();
    const int cnt2 = min(s_cnt2, 4096);
    const int N2 = (cnt2 <= 1024) ? 1024 : ((cnt2 <= 2048) ? 2048 : 4096);
    for (int i = tid; i < N2; i += 1024)
        if (i >= cnt2) s_buf[i] = 0ull;
    __syncthreads();

    for (int k = 2; k <= N2; k <<= 1) {
        for (int j = k >> 1; j > 0; j >>= 1) {
            for (int t = tid; t < N2; t += 1024) {
                int ixj = t ^ j;
                if (ixj > t) {
                    unsigned long long a = s_buf[t], b = s_buf[ixj];
                    bool up = (t & k) == 0;
                    if (up ? (a < b) : (a > b)) { s_buf[t] = b; s_buf[ixj] = a; }
                }
            }
            __syncthreads();
        }
    }

    if (tid < TOPK) {
        unsigned long long pk = (tid < cnt2) ? s_buf[tid] : 0ull;
        unsigned key = (unsigned)(pk >> 32);
        if (key == 0u) {
            g_score[n][tid] = 0.0f;
            g_label[n][tid] = 0;
            g_box[n][tid]  = make_float4(0.f, 0.f, 0.f, 0.f);
            g_obox[n][tid] = make_float4(0.f, 0.f, 0.f, 0.f);
        } else {
            unsigned idx = ~(unsigned)(pk & 0xffffffffull);
            int l = (int)(idx / NCLS), c = (int)(idx % NCLS);
            float sc = __uint_as_float(key);
            float lx = loc2[2 * l], ly = loc2[2 * l + 1];
            const float* rg = reg + (long long)n * 4 * HW;
            float r0 = rg[l], r1 = rg[HW + l], r2 = rg[2 * HW + l], r3 = rg[3 * HW + l];
            float ym = __fsub_rn((float)isz[2 * n],     1.0f);
            float xm = __fsub_rn((float)isz[2 * n + 1], 1.0f);
            float x1 = fminf(fmaxf(__fsub_rn(lx, r0), 0.0f), xm);
            float y1 = fminf(fmaxf(__fsub_rn(ly, r1), 0.0f), ym);
            float x2 = fminf(fmaxf(__fadd_rn(lx, r2), 0.0f), xm);
            float y2 = fminf(fmaxf(__fadd_rn(ly, r3), 0.0f), ym);
            int label = c + 1;
            float off = __fmul_rn((float)label, 100000.0f);
            g_score[n][tid] = sc;
            g_label[n][tid] = label;
            g_box[n][tid]  = make_float4(x1, y1, x2, y2);
            g_obox[n][tid] = make_float4(__fadd_rn(x1, off), __fadd_rn(y1, off),
                                         __fadd_rn(x2, off), __fadd_rn(y2, off));
        }
    }
}

// ---------------------------------------------------------------------------
// K5: per-class greedy NMS + keep prefix-scan + top-100 output
__global__ void __launch_bounds__(1024) k_nms_out(float* __restrict__ out) {
    __shared__ float4         s_ob[TOPK];
    __shared__ float          s_area[TOPK];
    __shared__ unsigned char  s_lab[TOPK];
    __shared__ unsigned char  s_supp[TOPK];
    __shared__ unsigned short s_pool[TOPK];
    __shared__ int            s_count[NCLS];
    __shared__ int            s_off[NCLS + 1];
    __shared__ int            s_scan[1024];

    const int n = blockIdx.x, tid = threadIdx.x, lane = tid & 31, w = tid >> 5;

    if (tid < NCLS) s_count[tid] = 0;
    if (tid < TOPK) {
        float4 b = g_obox[n][tid];
        s_ob[tid] = b;
        s_area[tid] = __fmul_rn(__fadd_rn(__fsub_rn(b.z, b.x), 1.0f),
                                __fadd_rn(__fsub_rn(b.w, b.y), 1.0f));
        int L = g_label[n][tid];
        s_lab[tid] = (unsigned char)L;
        s_supp[tid] = 0;
        if (L > 0) atomicAdd(&s_count[L - 1], 1);
    }
    __syncthreads();
    if (tid == 0) {
        int a = 0;
        for (int c = 0; c < NCLS; ++c) { s_off[c] = a; a += s_count[c]; }
        s_off[NCLS] = a;
    }
    __syncthreads();

    for (int c = w; c < NCLS; c += 32) {
        int off = s_off[c], cnt = 0;
        unsigned char want = (unsigned char)(c + 1);
        for (int base = 0; base < TOPK; base += 32) {
            int r = base + lane;
            bool hit = (r < TOPK) && (s_lab[r] == want);
            unsigned m = __ballot_sync(0xffffffffu, hit);
            if (hit) s_pool[off + cnt + __popc(m & ((1u << lane) - 1u))] = (unsigned short)r;
            cnt += __popc(m);
        }
    }
    __syncthreads();

    for (int c = w; c < NCLS; c += 32) {
        int off = s_off[c], m = s_count[c];
        for (int i = 0; i < m; ++i) {
            __syncwarp();
            int ri = s_pool[off + i];
            if (s_supp[ri]) continue;
            float4 bi = s_ob[ri];
            float  ai = s_area[ri];
            for (int j = i + 1 + lane; j < m; j += 32) {
                int rj = s_pool[off + j];
                float4 bj = s_ob[rj];
                float ww = __fadd_rn(__fsub_rn(fminf(bi.z, bj.z), fmaxf(bi.x, bj.x)), 1.0f);
                float hh = __fadd_rn(__fsub_rn(fminf(bi.w, bj.w), fmaxf(bi.y, bj.y)), 1.0f);
                ww = fmaxf(ww, 0.0f); hh = fmaxf(hh, 0.0f);
                float inter = __fmul_rn(ww, hh);
                float uni = __fsub_rn(__fadd_rn(ai, s_area[rj]), inter);
                float iou = __fdiv_rn(inter, uni);
                if (iou > 0.6f) s_supp[rj] = 1;
            }
        }
        __syncwarp();
    }
    __syncthreads();

    int keep = (tid < TOPK && s_lab[tid] > 0 && !s_supp[tid]) ? 1 : 0;
    s_scan[tid] = keep;
    __syncthreads();
    for (int off = 1; off < 1024; off <<= 1) {
        int v = (tid >= off) ? s_scan[tid - off] : 0;
        __syncthreads();
        s_scan[tid] += v;
        __syncthreads();
    }

    for (int i = tid; i < OUTK * 6; i += 1024) out[n * OUTK * 6 + i] = 0.0f;
    __syncthreads();

    if (keep) {
        int pos = s_scan[tid] - 1;
        if (pos < OUTK) {
            float4 b = g_box[n][tid];
            float* o = out + n * OUTK * 6 + pos * 6;
            o[0] = b.x; o[1] = b.y; o[2] = b.z; o[3] = b.w;
            o[4] = sqrtf(g_score[n][tid]);
            o[5] = (float)g_label[n][tid];
        }
    }
}

// ---------------------------------------------------------------------------
extern "C" void kernel_launch(void* const* d_in, const int* in_sizes, int n_in,
                              void* d_out, int out_size) {
    const float* locations = (const float*)d_in[0];
    const float* box_cls   = (const float*)d_in[1];
    const float* box_reg   = (const float*)d_in[2];
    const float* cent      = (const float*)d_in[3];
    const int*   isz       = (const int*)d_in[4];
    float* out = (float*)d_out;

    k_zero<<<NIMG, 256>>>();
    k_pass1<<<dim3(40, NIMG), 256>>>(box_cls, cent);
    k_cutoff<<<1, 32>>>();
    k_collect<<<dim3(400, NIMG), 256>>>(box_cls, cent);
    k_select<<<NIMG, 1024>>>(locations, box_reg, isz);
    k_nms_out<<<NIMG, 1024>>>(out);
}

// round 5
// speedup vs baseline: 1.5585x; 1.5585x over previous
#include <cuda_runtime.h>
#include <cstdint>

#define NIMG 8
#define NCLS 80
#define HW 40000
#define CAND_CAP 262144
#define TOPK 1000
#define OUTK 100
#define LINES_PP 1250            /* 128B lines per class plane (40000/32) */
#define LINES_PAD 1280
#define TAGS_PER_IMG (NCLS * LINES_PAD)   /* 102400 */
#define LINE_CAP 16384
#define STAGE_CAP 2048

#define XC_TAG  (-2.9446f)       /* conservative superset of p>0.05 */
#define XC_HIST (-2.9443f)       /* conservative subset of p>0.05  */
#define CBIN    (-4.76837158203125e-7f)   /* -4 * 2^-23 */
#define BIN_MARGIN 5

// ---------------- scratch (device globals; no allocation allowed) ----------
__device__ uint32_t            g_hist[NIMG][256];
__device__ int                 g_bcm[NIMG];
__device__ int                 g_cnt[NIMG];
__device__ int                 g_lcnt[NIMG];
__device__ int                 g_lines[NIMG][LINE_CAP];
__device__ unsigned char       g_tag[NIMG * TAGS_PER_IMG];
__device__ unsigned long long  g_cand[NIMG][CAND_CAP];
__device__ float               g_score[NIMG][TOPK];
__device__ int                 g_label[NIMG][TOPK];
__device__ float4              g_box[NIMG][TOPK];
__device__ float4              g_obox[NIMG][TOPK];

// exact sigmoid: XLA logistic expansion 1/(1+exp(-x)), IEEE div
__device__ __forceinline__ float sigm(float x) {
    return __fdiv_rn(1.0f, __fadd_rn(1.0f, expf(-x)));
}

// cheap scaled softplus-log: ~ 2^23 * log2(1 + e^-v). No MUFU, no div.
// Identical in pass1 and collect (bit-identical binning).
__device__ __forceinline__ float slog(float v) {
    float u  = v * -1.4426950408889634f;
    u = fmaxf(u, -126.0f);
    float fi = fmaf(u, 8388608.0f, 1065353216.0f);       // Schraudolph 2^u
    float ex = __int_as_float((int)fi);
    float w  = __fadd_rn(1.0f, ex);
    return (float)(__float_as_int(w) - 1065353216);      // ~= 2^23*log2(w)
}
__device__ __forceinline__ float bval(float sx, float sy) {
    return fmaf(sx + sy, CBIN, 256.0f);
}

// ---------------------------------------------------------------------------
__global__ void k_zero() {
    int t = blockIdx.x * blockDim.x + threadIdx.x;
    if (t < NIMG * 256) ((uint32_t*)g_hist)[t] = 0;
    if (t < NIMG) { g_cnt[t] = 0; g_lcnt[t] = 0; }
}

// ---------------------------------------------------------------------------
// Pass 1 (R2 version, unchanged): one full read of cls. Per-128B-line max bin
// -> 1-byte tag; line-level histogram for the cutoff.
__global__ void k_pass1(const float* __restrict__ cls, const float* __restrict__ cent) {
    __shared__ float    s_g[1024];
    __shared__ uint32_t s_hist[256];
    const int n = blockIdx.y, blk = blockIdx.x, tid = threadIdx.x;
    const int base = blk << 10;
    const int lim = min(1024, HW - base);

    for (int i = tid; i < 256; i += 256) s_hist[i] = 0;
    for (int i = tid; i < lim; i += 256)
        s_g[i] = slog(cent[n * HW + base + i]);
    __syncthreads();

    const float4* cls4 = (const float4*)cls;
    const int pf4 = (base >> 2) + tid;
    const bool act = pf4 < (HW / 4);
    const int gline = (blk << 5) + (tid >> 3);
    const bool lvalid = gline < LINES_PP;
    const int tagbase = n * TAGS_PER_IMG + gline;
    const int ibase = n * (NCLS * (HW / 4)) + pf4;

    float g0 = 0.f, g1 = 0.f, g2 = 0.f, g3 = 0.f;
    if (act) { g0 = s_g[tid*4]; g1 = s_g[tid*4+1]; g2 = s_g[tid*4+2]; g3 = s_g[tid*4+3]; }

    for (int c = 0; c < NCLS; ++c) {
        float tmax = -1e30f, hmax = -1e30f;
        if (act) {
            float4 v = cls4[ibase + c * (HW / 4)];
            float b0 = bval(slog(v.x), g0);
            float b1 = bval(slog(v.y), g1);
            float b2 = bval(slog(v.z), g2);
            float b3 = bval(slog(v.w), g3);
            if (v.x > XC_TAG)  tmax = fmaxf(tmax, b0);
            if (v.y > XC_TAG)  tmax = fmaxf(tmax, b1);
            if (v.z > XC_TAG)  tmax = fmaxf(tmax, b2);
            if (v.w > XC_TAG)  tmax = fmaxf(tmax, b3);
            if (v.x > XC_HIST) hmax = fmaxf(hmax, b0);
            if (v.y > XC_HIST) hmax = fmaxf(hmax, b1);
            if (v.z > XC_HIST) hmax = fmaxf(hmax, b2);
            if (v.w > XC_HIST) hmax = fmaxf(hmax, b3);
        }
        tmax = fmaxf(tmax, __shfl_xor_sync(0xffffffffu, tmax, 1));
        tmax = fmaxf(tmax, __shfl_xor_sync(0xffffffffu, tmax, 2));
        tmax = fmaxf(tmax, __shfl_xor_sync(0xffffffffu, tmax, 4));
        hmax = fmaxf(hmax, __shfl_xor_sync(0xffffffffu, hmax, 1));
        hmax = fmaxf(hmax, __shfl_xor_sync(0xffffffffu, hmax, 2));
        hmax = fmaxf(hmax, __shfl_xor_sync(0xffffffffu, hmax, 4));
        if ((tid & 7) == 0 && lvalid) {
            int tb = (int)floorf(tmax);
            tb = max(0, min(255, tb));
            g_tag[tagbase + c * LINES_PAD] = (unsigned char)tb;
            if (hmax > -1e29f) {
                int hb = max(0, min(255, (int)floorf(hmax)));
                atomicAdd(&s_hist[hb], 1u);
            }
        }
    }
    __syncthreads();
    for (int i = tid; i < 256; i += 256) {
        uint32_t v = s_hist[i];
        if (v) atomicAdd(&g_hist[n][i], v);
    }
}

// ---------------------------------------------------------------------------
// cutoff: highest bin with >=1000 lines above, minus safety margin
__global__ void k_cutoff() {
    int n = threadIdx.x;
    if (n >= NIMG) return;
    int cum[256];
    int acc = 0;
    for (int b = 255; b >= 0; --b) { acc += (int)g_hist[n][b]; cum[b] = acc; }
    int bcl = 0;
    for (int b = 255; b >= 0; --b) if (cum[b] >= TOPK) { bcl = b; break; }
    int m = bcl - BIN_MARGIN; if (m < 0) m = 0;
    while (m < bcl && 32 * cum[m] > CAND_CAP) ++m;   // capacity guard
    g_bcm[n] = m;
}

// ---------------------------------------------------------------------------
// k_scan: compact hit-line slots into g_lines. Block-aggregated: one global
// atomic per block (kills same-address atomic serialization).
__global__ void __launch_bounds__(256) k_scan() {
    __shared__ int s_list[2048];
    __shared__ int s_n, s_base;
    const int n = blockIdx.y, tid = threadIdx.x;
    const int slot0 = blockIdx.x * 2048;            // 50 blocks x 2048 = 102400
    const int bcm = g_bcm[n];
    if (tid == 0) s_n = 0;
    __syncthreads();

    const unsigned char* tags = &g_tag[n * TAGS_PER_IMG];
    for (int i = tid; i < 2048; i += 256) {
        int slot = slot0 + i;
        int l32 = slot % LINES_PAD;
        if (l32 < LINES_PP && (int)tags[slot] >= bcm) {
            int p = atomicAdd(&s_n, 1);             // smem atomic (cheap, sparse)
            s_list[p] = slot;
        }
    }
    __syncthreads();
    const int cnt = s_n;
    if (tid == 0 && cnt > 0) s_base = atomicAdd(&g_lcnt[n], cnt);
    __syncthreads();
    if (cnt > 0) {
        int base = s_base;
        for (int i = tid; i < cnt; i += 256) {
            int pos = base + i;
            if (pos < LINE_CAP) g_lines[n][pos] = s_list[i];
        }
    }
}

// ---------------------------------------------------------------------------
// k_lines: one warp per hit line (8 warps/block, tiled). Candidates staged in
// smem; flushed to g_cand with ONE global atomic per flush.
__global__ void __launch_bounds__(256) k_lines(const float* __restrict__ cls,
                                               const float* __restrict__ cent) {
    __shared__ unsigned long long s_stage[STAGE_CAP + 256];
    __shared__ int s_cnt, s_base;
    const int n = blockIdx.y, tid = threadIdx.x;
    const int lane = tid & 31, w = tid >> 5;
    const int lcnt = min(g_lcnt[n], LINE_CAP);
    const int bcm = g_bcm[n];
    const float fb = (float)bcm;
    if (tid == 0) s_cnt = 0;
    __syncthreads();

    for (int tile = blockIdx.x * 8; tile < lcnt; tile += 64 * 8) {
        int li = tile + w;
        if (li < lcnt) {
            int hslot = g_lines[n][li];
            int c = hslot / LINES_PAD, l = hslot % LINES_PAD;
            int wpos = l * 32 + lane;
            float x = cls[(n * NCLS + c) * HW + wpos];
            float y = cent[n * HW + wpos];
            bool sel = false;
            unsigned key = 0, idx = 0;
            if (x > XC_TAG) {
                float b = bval(slog(x), slog(y));        // bit-identical to pass1
                if (b >= fb) {
                    float p = sigm(x);                   // exact path for survivors
                    if (p > 0.05f) {
                        float sc = __fmul_rn(p, sigm(y));
                        key = __float_as_uint(sc);
                        idx = (unsigned)(wpos * NCLS + c);
                        sel = true;
                    }
                }
            }
            unsigned m = __ballot_sync(0xffffffffu, sel);
            if (sel) {
                int leader = __ffs(m) - 1;
                int rank = __popc(m & ((1u << lane) - 1u));
                int basep = 0;
                if (lane == leader) basep = atomicAdd(&s_cnt, __popc(m));  // smem
                basep = __shfl_sync(m, basep, leader);
                s_stage[basep + rank] = ((unsigned long long)key << 32) | (unsigned)(~idx);
            }
        }
        __syncthreads();
        if (s_cnt >= STAGE_CAP) {                        // flush (rare)
            int cnt = s_cnt;
            if (tid == 0) { s_base = atomicAdd(&g_cnt[n], cnt); s_cnt = 0; }
            __syncthreads();
            int base = s_base;
            for (int i = tid; i < cnt; i += 256) {
                int pos = base + i;
                if (pos < CAND_CAP) g_cand[n][pos] = s_stage[i];
            }
            __syncthreads();
        }
    }
    // final flush
    {
        int cnt = s_cnt;
        if (tid == 0 && cnt > 0) s_base = atomicAdd(&g_cnt[n], cnt);
        __syncthreads();
        if (cnt > 0) {
            int base = s_base;
            for (int i = tid; i < cnt; i += 256) {
                int pos = base + i;
                if (pos < CAND_CAP) g_cand[n][pos] = s_stage[i];
            }
        }
    }
}

// ---------------------------------------------------------------------------
// K4: exact top-1000 per image (maxkey-based fine hist -> refine -> bitonic),
// decode boxes
__global__ void __launch_bounds__(1024) k_select(const float* __restrict__ loc2,
                                                 const float* __restrict__ reg,
                                                 const int* __restrict__ isz) {
    __shared__ uint32_t s_hist[1024];
    __shared__ uint32_t s_cum[1024];
    __shared__ unsigned long long s_buf[4096];
    __shared__ unsigned s_wmax[32];
    __shared__ int s_cnt2, s_bf, s_rb;
    const int n = blockIdx.x, tid = threadIdx.x;
    const int Mn = min(g_cnt[n], CAND_CAP);

    s_hist[tid] = 0;
    if (tid == 0) { s_cnt2 = 0; s_bf = 0; }

    unsigned mk = 0;
    for (int i = tid; i < Mn; i += 1024) mk = max(mk, (unsigned)(g_cand[n][i] >> 32));
    for (int o = 16; o; o >>= 1) mk = max(mk, __shfl_xor_sync(0xffffffffu, mk, o));
    if ((tid & 31) == 0) s_wmax[tid >> 5] = mk;
    __syncthreads();
    if (tid == 0) {
        unsigned m2 = 0;
        for (int i = 0; i < 32; ++i) m2 = max(m2, s_wmax[i]);
        s_rb = (int)(m2 >> 17) - 1023;
    }
    __syncthreads();
    const int relbase = s_rb;

    for (int i = tid; i < Mn; i += 1024) {
        unsigned key = (unsigned)(g_cand[n][i] >> 32);
        int rel = (int)(key >> 17) - relbase;
        if (rel >= 0) atomicAdd(&s_hist[rel], 1u);
    }
    __syncthreads();

    s_cum[tid] = s_hist[tid];
    __syncthreads();
    for (int off = 1; off < 1024; off <<= 1) {
        uint32_t add = (tid + off < 1024) ? s_cum[tid + off] : 0u;
        __syncthreads();
        s_cum[tid] += add;
        __syncthreads();
    }
    const int total = (int)s_cum[0];
    const int target = min(TOPK, total);
    if (target > 0) {
        if ((int)s_cum[tid] >= target && (tid == 1023 || (int)s_cum[tid + 1] < target))
            s_bf = tid;
    }
    __syncthreads();
    const int bf = s_bf;

    for (int i = tid; i < Mn; i += 1024) {
        unsigned long long pk = g_cand[n][i];
        int rel = (int)((unsigned)(pk >> 32) >> 17) - relbase;
        if (rel >= bf) {
            int p = atomicAdd(&s_cnt2, 1);
            if (p < 4096) s_buf[p] = pk;
        }
    }
    __syncthreads();
    const int cnt2 = min(s_cnt2, 4096);
    const int N2 = (cnt2 <= 1024) ? 1024 : ((cnt2 <= 2048) ? 2048 : 4096);
    for (int i = tid; i < N2; i += 1024)
        if (i >= cnt2) s_buf[i] = 0ull;
    __syncthreads();

    for (int k = 2; k <= N2; k <<= 1) {
        for (int j = k >> 1; j > 0; j >>= 1) {
            for (int t = tid; t < N2; t += 1024) {
                int ixj = t ^ j;
                if (ixj > t) {
                    unsigned long long a = s_buf[t], b = s_buf[ixj];
                    bool up = (t & k) == 0;
                    if (up ? (a < b) : (a > b)) { s_buf[t] = b; s_buf[ixj] = a; }
                }
            }
            __syncthreads();
        }
    }

    if (tid < TOPK) {
        unsigned long long pk = (tid < cnt2) ? s_buf[tid] : 0ull;
        unsigned key = (unsigned)(pk >> 32);
        if (key == 0u) {
            g_score[n][tid] = 0.0f;
            g_label[n][tid] = 0;
            g_box[n][tid]  = make_float4(0.f, 0.f, 0.f, 0.f);
            g_obox[n][tid] = make_float4(0.f, 0.f, 0.f, 0.f);
        } else {
            unsigned idx = ~(unsigned)(pk & 0xffffffffull);
            int l = (int)(idx / NCLS), c = (int)(idx % NCLS);
            float sc = __uint_as_float(key);
            float lx = loc2[2 * l], ly = loc2[2 * l + 1];
            const float* rg = reg + (long long)n * 4 * HW;
            float r0 = rg[l], r1 = rg[HW + l], r2 = rg[2 * HW + l], r3 = rg[3 * HW + l];
            float ym = __fsub_rn((float)isz[2 * n],     1.0f);
            float xm = __fsub_rn((float)isz[2 * n + 1], 1.0f);
            float x1 = fminf(fmaxf(__fsub_rn(lx, r0), 0.0f), xm);
            float y1 = fminf(fmaxf(__fsub_rn(ly, r1), 0.0f), ym);
            float x2 = fminf(fmaxf(__fadd_rn(lx, r2), 0.0f), xm);
            float y2 = fminf(fmaxf(__fadd_rn(ly, r3), 0.0f), ym);
            int label = c + 1;
            float off = __fmul_rn((float)label, 100000.0f);
            g_score[n][tid] = sc;
            g_label[n][tid] = label;
            g_box[n][tid]  = make_float4(x1, y1, x2, y2);
            g_obox[n][tid] = make_float4(__fadd_rn(x1, off), __fadd_rn(y1, off),
                                         __fadd_rn(x2, off), __fadd_rn(y2, off));
        }
    }
}

// ---------------------------------------------------------------------------
// K5: per-class greedy NMS + keep prefix-scan + top-100 output
__global__ void __launch_bounds__(1024) k_nms_out(float* __restrict__ out) {
    __shared__ float4         s_ob[TOPK];
    __shared__ float          s_area[TOPK];
    __shared__ unsigned char  s_lab[TOPK];
    __shared__ unsigned char  s_supp[TOPK];
    __shared__ unsigned short s_pool[TOPK];
    __shared__ int            s_count[NCLS];
    __shared__ int            s_off[NCLS + 1];
    __shared__ int            s_scan[1024];

    const int n = blockIdx.x, tid = threadIdx.x, lane = tid & 31, w = tid >> 5;

    if (tid < NCLS) s_count[tid] = 0;
    if (tid < TOPK) {
        float4 b = g_obox[n][tid];
        s_ob[tid] = b;
        s_area[tid] = __fmul_rn(__fadd_rn(__fsub_rn(b.z, b.x), 1.0f),
                                __fadd_rn(__fsub_rn(b.w, b.y), 1.0f));
        int L = g_label[n][tid];
        s_lab[tid] = (unsigned char)L;
        s_supp[tid] = 0;
        if (L > 0) atomicAdd(&s_count[L - 1], 1);
    }
    __syncthreads();
    if (tid == 0) {
        int a = 0;
        for (int c = 0; c < NCLS; ++c) { s_off[c] = a; a += s_count[c]; }
        s_off[NCLS] = a;
    }
    __syncthreads();

    for (int c = w; c < NCLS; c += 32) {
        int off = s_off[c], cnt = 0;
        unsigned char want = (unsigned char)(c + 1);
        for (int base = 0; base < TOPK; base += 32) {
            int r = base + lane;
            bool hit = (r < TOPK) && (s_lab[r] == want);
            unsigned m = __ballot_sync(0xffffffffu, hit);
            if (hit) s_pool[off + cnt + __popc(m & ((1u << lane) - 1u))] = (unsigned short)r;
            cnt += __popc(m);
        }
    }
    __syncthreads();

    for (int c = w; c < NCLS; c += 32) {
        int off = s_off[c], m = s_count[c];
        for (int i = 0; i < m; ++i) {
            __syncwarp();
            int ri = s_pool[off + i];
            if (s_supp[ri]) continue;
            float4 bi = s_ob[ri];
            float  ai = s_area[ri];
            for (int j = i + 1 + lane; j < m; j += 32) {
                int rj = s_pool[off + j];
                float4 bj = s_ob[rj];
                float ww = __fadd_rn(__fsub_rn(fminf(bi.z, bj.z), fmaxf(bi.x, bj.x)), 1.0f);
                float hh = __fadd_rn(__fsub_rn(fminf(bi.w, bj.w), fmaxf(bi.y, bj.y)), 1.0f);
                ww = fmaxf(ww, 0.0f); hh = fmaxf(hh, 0.0f);
                float inter = __fmul_rn(ww, hh);
                float uni = __fsub_rn(__fadd_rn(ai, s_area[rj]), inter);
                float iou = __fdiv_rn(inter, uni);
                if (iou > 0.6f) s_supp[rj] = 1;
            }
        }
        __syncwarp();
    }
    __syncthreads();

    int keep = (tid < TOPK && s_lab[tid] > 0 && !s_supp[tid]) ? 1 : 0;
    s_scan[tid] = keep;
    __syncthreads();
    for (int off = 1; off < 1024; off <<= 1) {
        int v = (tid >= off) ? s_scan[tid - off] : 0;
        __syncthreads();
        s_scan[tid] += v;
        __syncthreads();
    }

    for (int i = tid; i < OUTK * 6; i += 1024) out[n * OUTK * 6 + i] = 0.0f;
    __syncthreads();

    if (keep) {
        int pos = s_scan[tid] - 1;
        if (pos < OUTK) {
            float4 b = g_box[n][tid];
            float* o = out + n * OUTK * 6 + pos * 6;
            o[0] = b.x; o[1] = b.y; o[2] = b.z; o[3] = b.w;
            o[4] = sqrtf(g_score[n][tid]);
            o[5] = (float)g_label[n][tid];
        }
    }
}

// ---------------------------------------------------------------------------
extern "C" void kernel_launch(void* const* d_in, const int* in_sizes, int n_in,
                              void* d_out, int out_size) {
    const float* locations = (const float*)d_in[0];
    const float* box_cls   = (const float*)d_in[1];
    const float* box_reg   = (const float*)d_in[2];
    const float* cent      = (const float*)d_in[3];
    const int*   isz       = (const int*)d_in[4];
    float* out = (float*)d_out;

    k_zero<<<NIMG, 256>>>();
    k_pass1<<<dim3(40, NIMG), 256>>>(box_cls, cent);
    k_cutoff<<<1, 32>>>();
    k_scan<<<dim3(50, NIMG), 256>>>();
    k_lines<<<dim3(64, NIMG), 256>>>(box_cls, cent);
    k_select<<<NIMG, 1024>>>(locations, box_reg, isz);
    k_nms_out<<<NIMG, 1024>>>(out);
}

// round 6
// speedup vs baseline: 1.7669x; 1.1337x over previous
#include <cuda_runtime.h>
#include <cstdint>

#define NIMG 8
#define NCLS 80
#define HW 40000
#define CAND_CAP 262144
#define TOPK 1000
#define OUTK 100
#define LINES_PP 1250            /* 128B lines per class plane (40000/32) */
#define LINES_PAD 1280
#define TAGS_PER_IMG (NCLS * LINES_PAD)   /* 102400 */
#define LINE_CAP 16384
#define STAGE_CAP 2048

#define XC_TAG  (-2.9446f)       /* conservative superset of p>0.05 */
#define XC_HIST (-2.9443f)       /* conservative subset of p>0.05  */
#define CBIN    (-4.76837158203125e-7f)   /* -4 * 2^-23 */
#define BIN_MARGIN 5

// ---------------- scratch (device globals; no allocation allowed) ----------
__device__ uint32_t            g_hist[NIMG][256];
__device__ int                 g_bcm[NIMG];
__device__ int                 g_cnt[NIMG];
__device__ int                 g_lcnt[NIMG];
__device__ int                 g_lines[NIMG][LINE_CAP];
__device__ unsigned char       g_tag[NIMG * TAGS_PER_IMG];
__device__ unsigned long long  g_cand[NIMG][CAND_CAP];
__device__ float               g_score[NIMG][TOPK];
__device__ int                 g_label[NIMG][TOPK];
__device__ float4              g_box[NIMG][TOPK];
__device__ float4              g_obox[NIMG][TOPK];

// exact sigmoid: XLA logistic expansion 1/(1+exp(-x)), IEEE div
__device__ __forceinline__ float sigm(float x) {
    return __fdiv_rn(1.0f, __fadd_rn(1.0f, expf(-x)));
}

// cheap scaled softplus-log: ~ 2^23 * log2(1 + e^-v). No MUFU, no div.
// Identical in pass1 and collect (bit-identical binning).
__device__ __forceinline__ float slog(float v) {
    float u  = v * -1.4426950408889634f;
    u = fmaxf(u, -126.0f);
    float fi = fmaf(u, 8388608.0f, 1065353216.0f);       // Schraudolph 2^u
    float ex = __int_as_float((int)fi);
    float w  = __fadd_rn(1.0f, ex);
    return (float)(__float_as_int(w) - 1065353216);      // ~= 2^23*log2(w)
}
__device__ __forceinline__ float bval(float sx, float sy) {
    return fmaf(sx + sy, CBIN, 256.0f);
}

// ---------------------------------------------------------------------------
// Pass 1: one full read of cls. 512 threads/block: two thread-halves process
// two classes per iteration (identical tag/hist semantics to the 256-thread
// version; 2x warps for latency hiding).
__global__ void __launch_bounds__(512) k_pass1(const float* __restrict__ cls,
                                               const float* __restrict__ cent) {
    __shared__ float    s_g[1024];
    __shared__ uint32_t s_hist[256];
    const int n = blockIdx.y, blk = blockIdx.x, tid = threadIdx.x;
    const int htid = tid & 255;                 // index within half
    const int cpar = tid >> 8;                  // 0 or 1: class parity
    const int base = blk << 10;
    const int lim = min(1024, HW - base);

    for (int i = tid; i < 256; i += 512) s_hist[i] = 0;
    for (int i = tid; i < lim; i += 512)
        s_g[i] = slog(cent[n * HW + base + i]);
    __syncthreads();

    const float4* cls4 = (const float4*)cls;
    const int pf4 = (base >> 2) + htid;
    const bool act = pf4 < (HW / 4);
    const int gline = (blk << 5) + (htid >> 3);
    const bool lvalid = gline < LINES_PP;
    const int tagbase = n * TAGS_PER_IMG + gline;
    const int ibase = n * (NCLS * (HW / 4)) + pf4;

    float g0 = 0.f, g1 = 0.f, g2 = 0.f, g3 = 0.f;
    if (act) { g0 = s_g[htid*4]; g1 = s_g[htid*4+1]; g2 = s_g[htid*4+2]; g3 = s_g[htid*4+3]; }

    for (int cc = 0; cc < NCLS; cc += 2) {
        const int c = cc + cpar;
        float tmax = -1e30f, hmax = -1e30f;
        if (act) {
            float4 v = cls4[ibase + c * (HW / 4)];
            float b0 = bval(slog(v.x), g0);
            float b1 = bval(slog(v.y), g1);
            float b2 = bval(slog(v.z), g2);
            float b3 = bval(slog(v.w), g3);
            if (v.x > XC_TAG)  tmax = fmaxf(tmax, b0);
            if (v.y > XC_TAG)  tmax = fmaxf(tmax, b1);
            if (v.z > XC_TAG)  tmax = fmaxf(tmax, b2);
            if (v.w > XC_TAG)  tmax = fmaxf(tmax, b3);
            if (v.x > XC_HIST) hmax = fmaxf(hmax, b0);
            if (v.y > XC_HIST) hmax = fmaxf(hmax, b1);
            if (v.z > XC_HIST) hmax = fmaxf(hmax, b2);
            if (v.w > XC_HIST) hmax = fmaxf(hmax, b3);
        }
        tmax = fmaxf(tmax, __shfl_xor_sync(0xffffffffu, tmax, 1));
        tmax = fmaxf(tmax, __shfl_xor_sync(0xffffffffu, tmax, 2));
        tmax = fmaxf(tmax, __shfl_xor_sync(0xffffffffu, tmax, 4));
        hmax = fmaxf(hmax, __shfl_xor_sync(0xffffffffu, hmax, 1));
        hmax = fmaxf(hmax, __shfl_xor_sync(0xffffffffu, hmax, 2));
        hmax = fmaxf(hmax, __shfl_xor_sync(0xffffffffu, hmax, 4));
        if ((htid & 7) == 0 && lvalid) {
            int tb = (int)floorf(tmax);
            tb = max(0, min(255, tb));
            g_tag[tagbase + c * LINES_PAD] = (unsigned char)tb;
            if (hmax > -1e29f) {
                int hb = max(0, min(255, (int)floorf(hmax)));
                atomicAdd(&s_hist[hb], 1u);
            }
        }
    }
    __syncthreads();
    for (int i = tid; i < 256; i += 512) {
        uint32_t v = s_hist[i];
        if (v) atomicAdd(&g_hist[n][i], v);
    }
}

// ---------------------------------------------------------------------------
// cutoff: highest bin with >=1000 lines above, minus safety margin.
// Also SELF-RESETS g_hist/g_cnt/g_lcnt for the next graph replay
// (device globals start zeroed; every call leaves them zeroed => deterministic).
__global__ void k_cutoff() {
    int n = threadIdx.x;
    if (n >= NIMG) return;
    int cum[256];
    int acc = 0;
    for (int b = 255; b >= 0; --b) { acc += (int)g_hist[n][b]; cum[b] = acc; }
    int bcl = 0;
    for (int b = 255; b >= 0; --b) if (cum[b] >= TOPK) { bcl = b; break; }
    int m = bcl - BIN_MARGIN; if (m < 0) m = 0;
    while (m < bcl && 32 * cum[m] > CAND_CAP) ++m;   // capacity guard
    g_bcm[n] = m;
    // reset for next replay / this run's later stages
    for (int b = 0; b < 256; ++b) g_hist[n][b] = 0;
    g_cnt[n] = 0;
    g_lcnt[n] = 0;
}

// ---------------------------------------------------------------------------
// k_scan: compact hit-line slots into g_lines. Block-aggregated: one global
// atomic per block.
__global__ void __launch_bounds__(256) k_scan() {
    __shared__ int s_list[2048];
    __shared__ int s_n, s_base;
    const int n = blockIdx.y, tid = threadIdx.x;
    const int slot0 = blockIdx.x * 2048;            // 50 blocks x 2048 = 102400
    const int bcm = g_bcm[n];
    if (tid == 0) s_n = 0;
    __syncthreads();

    const unsigned char* tags = &g_tag[n * TAGS_PER_IMG];
    for (int i = tid; i < 2048; i += 256) {
        int slot = slot0 + i;
        int l32 = slot % LINES_PAD;
        if (l32 < LINES_PP && (int)tags[slot] >= bcm) {
            int p = atomicAdd(&s_n, 1);             // smem atomic (cheap, sparse)
            s_list[p] = slot;
        }
    }
    __syncthreads();
    const int cnt = s_n;
    if (tid == 0 && cnt > 0) s_base = atomicAdd(&g_lcnt[n], cnt);
    __syncthreads();
    if (cnt > 0) {
        int base = s_base;
        for (int i = tid; i < cnt; i += 256) {
            int pos = base + i;
            if (pos < LINE_CAP) g_lines[n][pos] = s_list[i];
        }
    }
}

// ---------------------------------------------------------------------------
// k_lines: one warp per hit line (8 warps/block, tiled). Candidates staged in
// smem; flushed to g_cand with ONE global atomic per flush.
__global__ void __launch_bounds__(256) k_lines(const float* __restrict__ cls,
                                               const float* __restrict__ cent) {
    __shared__ unsigned long long s_stage[STAGE_CAP + 256];
    __shared__ int s_cnt, s_base;
    const int n = blockIdx.y, tid = threadIdx.x;
    const int lane = tid & 31, w = tid >> 5;
    const int lcnt = min(g_lcnt[n], LINE_CAP);
    const int bcm = g_bcm[n];
    const float fb = (float)bcm;
    if (tid == 0) s_cnt = 0;
    __syncthreads();

    for (int tile = blockIdx.x * 8; tile < lcnt; tile += 64 * 8) {
        int li = tile + w;
        if (li < lcnt) {
            int hslot = g_lines[n][li];
            int c = hslot / LINES_PAD, l = hslot % LINES_PAD;
            int wpos = l * 32 + lane;
            float x = cls[(n * NCLS + c) * HW + wpos];
            float y = cent[n * HW + wpos];
            bool sel = false;
            unsigned key = 0, idx = 0;
            if (x > XC_TAG) {
                float b = bval(slog(x), slog(y));        // bit-identical to pass1
                if (b >= fb) {
                    float p = sigm(x);                   // exact path for survivors
                    if (p > 0.05f) {
                        float sc = __fmul_rn(p, sigm(y));
                        key = __float_as_uint(sc);
                        idx = (unsigned)(wpos * NCLS + c);
                        sel = true;
                    }
                }
            }
            unsigned m = __ballot_sync(0xffffffffu, sel);
            if (sel) {
                int leader = __ffs(m) - 1;
                int rank = __popc(m & ((1u << lane) - 1u));
                int basep = 0;
                if (lane == leader) basep = atomicAdd(&s_cnt, __popc(m));  // smem
                basep = __shfl_sync(m, basep, leader);
                s_stage[basep + rank] = ((unsigned long long)key << 32) | (unsigned)(~idx);
            }
        }
        __syncthreads();
        if (s_cnt >= STAGE_CAP) {                        // flush (rare)
            int cnt = s_cnt;
            if (tid == 0) { s_base = atomicAdd(&g_cnt[n], cnt); s_cnt = 0; }
            __syncthreads();
            int base = s_base;
            for (int i = tid; i < cnt; i += 256) {
                int pos = base + i;
                if (pos < CAND_CAP) g_cand[n][pos] = s_stage[i];
            }
            __syncthreads();
        }
    }
    // final flush
    {
        int cnt = s_cnt;
        if (tid == 0 && cnt > 0) s_base = atomicAdd(&g_cnt[n], cnt);
        __syncthreads();
        if (cnt > 0) {
            int base = s_base;
            for (int i = tid; i < cnt; i += 256) {
                int pos = base + i;
                if (pos < CAND_CAP) g_cand[n][pos] = s_stage[i];
            }
        }
    }
}

// ---------------------------------------------------------------------------
// K4: exact top-1000 per image (maxkey-based fine hist -> refine -> bitonic),
// decode boxes
__global__ void __launch_bounds__(1024) k_select(const float* __restrict__ loc2,
                                                 const float* __restrict__ reg,
                                                 const int* __restrict__ isz) {
    __shared__ uint32_t s_hist[1024];
    __shared__ uint32_t s_cum[1024];
    __shared__ unsigned long long s_buf[4096];
    __shared__ unsigned s_wmax[32];
    __shared__ int s_cnt2, s_bf, s_rb;
    const int n = blockIdx.x, tid = threadIdx.x;
    const int Mn = min(g_cnt[n], CAND_CAP);

    s_hist[tid] = 0;
    if (tid == 0) { s_cnt2 = 0; s_bf = 0; }

    unsigned mk = 0;
    for (int i = tid; i < Mn; i += 1024) mk = max(mk, (unsigned)(g_cand[n][i] >> 32));
    for (int o = 16; o; o >>= 1) mk = max(mk, __shfl_xor_sync(0xffffffffu, mk, o));
    if ((tid & 31) == 0) s_wmax[tid >> 5] = mk;
    __syncthreads();
    if (tid == 0) {
        unsigned m2 = 0;
        for (int i = 0; i < 32; ++i) m2 = max(m2, s_wmax[i]);
        s_rb = (int)(m2 >> 17) - 1023;
    }
    __syncthreads();
    const int relbase = s_rb;

    for (int i = tid; i < Mn; i += 1024) {
        unsigned key = (unsigned)(g_cand[n][i] >> 32);
        int rel = (int)(key >> 17) - relbase;
        if (rel >= 0) atomicAdd(&s_hist[rel], 1u);
    }
    __syncthreads();

    s_cum[tid] = s_hist[tid];
    __syncthreads();
    for (int off = 1; off < 1024; off <<= 1) {
        uint32_t add = (tid + off < 1024) ? s_cum[tid + off] : 0u;
        __syncthreads();
        s_cum[tid] += add;
        __syncthreads();
    }
    const int total = (int)s_cum[0];
    const int target = min(TOPK, total);
    if (target > 0) {
        if ((int)s_cum[tid] >= target && (tid == 1023 || (int)s_cum[tid + 1] < target))
            s_bf = tid;
    }
    __syncthreads();
    const int bf = s_bf;

    for (int i = tid; i < Mn; i += 1024) {
        unsigned long long pk = g_cand[n][i];
        int rel = (int)((unsigned)(pk >> 32) >> 17) - relbase;
        if (rel >= bf) {
            int p = atomicAdd(&s_cnt2, 1);
            if (p < 4096) s_buf[p] = pk;
        }
    }
    __syncthreads();
    const int cnt2 = min(s_cnt2, 4096);
    const int N2 = (cnt2 <= 1024) ? 1024 : ((cnt2 <= 2048) ? 2048 : 4096);
    for (int i = tid; i < N2; i += 1024)
        if (i >= cnt2) s_buf[i] = 0ull;
    __syncthreads();

    for (int k = 2; k <= N2; k <<= 1) {
        for (int j = k >> 1; j > 0; j >>= 1) {
            for (int t = tid; t < N2; t += 1024) {
                int ixj = t ^ j;
                if (ixj > t) {
                    unsigned long long a = s_buf[t], b = s_buf[ixj];
                    bool up = (t & k) == 0;
                    if (up ? (a < b) : (a > b)) { s_buf[t] = b; s_buf[ixj] = a; }
                }
            }
            __syncthreads();
        }
    }

    if (tid < TOPK) {
        unsigned long long pk = (tid < cnt2) ? s_buf[tid] : 0ull;
        unsigned key = (unsigned)(pk >> 32);
        if (key == 0u) {
            g_score[n][tid] = 0.0f;
            g_label[n][tid] = 0;
            g_box[n][tid]  = make_float4(0.f, 0.f, 0.f, 0.f);
            g_obox[n][tid] = make_float4(0.f, 0.f, 0.f, 0.f);
        } else {
            unsigned idx = ~(unsigned)(pk & 0xffffffffull);
            int l = (int)(idx / NCLS), c = (int)(idx % NCLS);
            float sc = __uint_as_float(key);
            float lx = loc2[2 * l], ly = loc2[2 * l + 1];
            const float* rg = reg + (long long)n * 4 * HW;
            float r0 = rg[l], r1 = rg[HW + l], r2 = rg[2 * HW + l], r3 = rg[3 * HW + l];
            float ym = __fsub_rn((float)isz[2 * n],     1.0f);
            float xm = __fsub_rn((float)isz[2 * n + 1], 1.0f);
            float x1 = fminf(fmaxf(__fsub_rn(lx, r0), 0.0f), xm);
            float y1 = fminf(fmaxf(__fsub_rn(ly, r1), 0.0f), ym);
            float x2 = fminf(fmaxf(__fadd_rn(lx, r2), 0.0f), xm);
            float y2 = fminf(fmaxf(__fadd_rn(ly, r3), 0.0f), ym);
            int label = c + 1;
            float off = __fmul_rn((float)label, 100000.0f);
            g_score[n][tid] = sc;
            g_label[n][tid] = label;
            g_box[n][tid]  = make_float4(x1, y1, x2, y2);
            g_obox[n][tid] = make_float4(__fadd_rn(x1, off), __fadd_rn(y1, off),
                                         __fadd_rn(x2, off), __fadd_rn(y2, off));
        }
    }
}

// ---------------------------------------------------------------------------
// K5: per-class greedy NMS + keep prefix-scan + top-100 output
__global__ void __launch_bounds__(1024) k_nms_out(float* __restrict__ out) {
    __shared__ float4         s_ob[TOPK];
    __shared__ float          s_area[TOPK];
    __shared__ unsigned char  s_lab[TOPK];
    __shared__ unsigned char  s_supp[TOPK];
    __shared__ unsigned short s_pool[TOPK];
    __shared__ int            s_count[NCLS];
    __shared__ int            s_off[NCLS + 1];
    __shared__ int            s_scan[1024];

    const int n = blockIdx.x, tid = threadIdx.x, lane = tid & 31, w = tid >> 5;

    if (tid < NCLS) s_count[tid] = 0;
    if (tid < TOPK) {
        float4 b = g_obox[n][tid];
        s_ob[tid] = b;
        s_area[tid] = __fmul_rn(__fadd_rn(__fsub_rn(b.z, b.x), 1.0f),
                                __fadd_rn(__fsub_rn(b.w, b.y), 1.0f));
        int L = g_label[n][tid];
        s_lab[tid] = (unsigned char)L;
        s_supp[tid] = 0;
        if (L > 0) atomicAdd(&s_count[L - 1], 1);
    }
    __syncthreads();
    if (tid == 0) {
        int a = 0;
        for (int c = 0; c < NCLS; ++c) { s_off[c] = a; a += s_count[c]; }
        s_off[NCLS] = a;
    }
    __syncthreads();

    for (int c = w; c < NCLS; c += 32) {
        int off = s_off[c], cnt = 0;
        unsigned char want = (unsigned char)(c + 1);
        for (int base = 0; base < TOPK; base += 32) {
            int r = base + lane;
            bool hit = (r < TOPK) && (s_lab[r] == want);
            unsigned m = __ballot_sync(0xffffffffu, hit);
            if (hit) s_pool[off + cnt + __popc(m & ((1u << lane) - 1u))] = (unsigned short)r;
            cnt += __popc(m);
        }
    }
    __syncthreads();

    for (int c = w; c < NCLS; c += 32) {
        int off = s_off[c], m = s_count[c];
        for (int i = 0; i < m; ++i) {
            __syncwarp();
            int ri = s_pool[off + i];
            if (s_supp[ri]) continue;
            float4 bi = s_ob[ri];
            float  ai = s_area[ri];
            for (int j = i + 1 + lane; j < m; j += 32) {
                int rj = s_pool[off + j];
                float4 bj = s_ob[rj];
                float ww = __fadd_rn(__fsub_rn(fminf(bi.z, bj.z), fmaxf(bi.x, bj.x)), 1.0f);
                float hh = __fadd_rn(__fsub_rn(fminf(bi.w, bj.w), fmaxf(bi.y, bj.y)), 1.0f);
                ww = fmaxf(ww, 0.0f); hh = fmaxf(hh, 0.0f);
                float inter = __fmul_rn(ww, hh);
                float uni = __fsub_rn(__fadd_rn(ai, s_area[rj]), inter);
                float iou = __fdiv_rn(inter, uni);
                if (iou > 0.6f) s_supp[rj] = 1;
            }
        }
        __syncwarp();
    }
    __syncthreads();

    int keep = (tid < TOPK && s_lab[tid] > 0 && !s_supp[tid]) ? 1 : 0;
    s_scan[tid] = keep;
    __syncthreads();
    for (int off = 1; off < 1024; off <<= 1) {
        int v = (tid >= off) ? s_scan[tid - off] : 0;
        __syncthreads();
        s_scan[tid] += v;
        __syncthreads();
    }

    for (int i = tid; i < OUTK * 6; i += 1024) out[n * OUTK * 6 + i] = 0.0f;
    __syncthreads();

    if (keep) {
        int pos = s_scan[tid] - 1;
        if (pos < OUTK) {
            float4 b = g_box[n][tid];
            float* o = out + n * OUTK * 6 + pos * 6;
            o[0] = b.x; o[1] = b.y; o[2] = b.z; o[3] = b.w;
            o[4] = sqrtf(g_score[n][tid]);
            o[5] = (float)g_label[n][tid];
        }
    }
}

// ---------------------------------------------------------------------------
extern "C" void kernel_launch(void* const* d_in, const int* in_sizes, int n_in,
                              void* d_out, int out_size) {
    const float* locations = (const float*)d_in[0];
    const float* box_cls   = (const float*)d_in[1];
    const float* box_reg   = (const float*)d_in[2];
    const float* cent      = (const float*)d_in[3];
    const int*   isz       = (const int*)d_in[4];
    float* out = (float*)d_out;

    k_pass1<<<dim3(40, NIMG), 512>>>(box_cls, cent);
    k_cutoff<<<1, 32>>>();
    k_scan<<<dim3(50, NIMG), 256>>>();
    k_lines<<<dim3(64, NIMG), 256>>>(box_cls, cent);
    k_select<<<NIMG, 1024>>>(locations, box_reg, isz);
    k_nms_out<<<NIMG, 1024>>>(out);
}

// round 8
// speedup vs baseline: 1.8820x; 1.0651x over previous
#include <cuda_runtime.h>
#include <cstdint>

#define NIMG 8
#define NCLS 80
#define HW 40000
#define CAND_CAP 262144
#define TOPK 1000
#define OUTK 100
#define LINES_PP 1250            /* 128B lines per class plane (40000/32) */
#define LINES_PAD 1280
#define TAGS_PER_IMG (NCLS * LINES_PAD)   /* 102400 */
#define LINE_CAP 16384
#define CHUNK 64                 /* lines per k_lines block; 64*32 = 2048 = stage cap */

#define XC_TAG  (-2.9446f)       /* conservative superset of p>0.05 */
#define XC_HIST (-2.9443f)       /* conservative subset of p>0.05  */
#define CBIN    (-4.76837158203125e-7f)   /* -4 * 2^-23 */
#define BIN_MARGIN 5

// ---------------- scratch (device globals; no allocation allowed) ----------
__device__ uint32_t            g_hist[NIMG][256];
__device__ int                 g_bcm[NIMG];
__device__ int                 g_cnt[NIMG];
__device__ int                 g_lcnt[NIMG];
__device__ int                 g_lines[NIMG][LINE_CAP];
__device__ unsigned char       g_tag[NIMG * TAGS_PER_IMG];
__device__ unsigned long long  g_cand[NIMG][CAND_CAP];
__device__ float               g_score[NIMG][TOPK];
__device__ int                 g_label[NIMG][TOPK];
__device__ float4              g_box[NIMG][TOPK];
__device__ float4              g_obox[NIMG][TOPK];

// exact sigmoid: XLA logistic expansion 1/(1+exp(-x)), IEEE div
__device__ __forceinline__ float sigm(float x) {
    return __fdiv_rn(1.0f, __fadd_rn(1.0f, expf(-x)));
}

// cheap scaled softplus-log: ~ 2^23 * log2(1 + e^-v). No MUFU, no div.
// Identical in pass1 and collect (bit-identical binning).
__device__ __forceinline__ float slog(float v) {
    float u  = v * -1.4426950408889634f;
    u = fmaxf(u, -126.0f);
    float fi = fmaf(u, 8388608.0f, 1065353216.0f);       // Schraudolph 2^u
    float ex = __int_as_float((int)fi);
    float w  = __fadd_rn(1.0f, ex);
    return (float)(__float_as_int(w) - 1065353216);      // ~= 2^23*log2(w)
}
__device__ __forceinline__ float bval(float sx, float sy) {
    return fmaf(sx + sy, CBIN, 256.0f);
}

// ---------------------------------------------------------------------------
// Pass 1: one full read of cls. 512 threads/block: two thread-halves process
// two classes per iteration.
__global__ void __launch_bounds__(512) k_pass1(const float* __restrict__ cls,
                                               const float* __restrict__ cent) {
    __shared__ float    s_g[1024];
    __shared__ uint32_t s_hist[256];
    const int n = blockIdx.y, blk = blockIdx.x, tid = threadIdx.x;
    const int htid = tid & 255;                 // index within half
    const int cpar = tid >> 8;                  // 0 or 1: class parity
    const int base = blk << 10;
    const int lim = min(1024, HW - base);

    for (int i = tid; i < 256; i += 512) s_hist[i] = 0;
    for (int i = tid; i < lim; i += 512)
        s_g[i] = slog(cent[n * HW + base + i]);
    __syncthreads();

    const float4* cls4 = (const float4*)cls;
    const int pf4 = (base >> 2) + htid;
    const bool act = pf4 < (HW / 4);
    const int gline = (blk << 5) + (htid >> 3);
    const bool lvalid = gline < LINES_PP;
    const int tagbase = n * TAGS_PER_IMG + gline;
    const int ibase = n * (NCLS * (HW / 4)) + pf4;

    float g0 = 0.f, g1 = 0.f, g2 = 0.f, g3 = 0.f;
    if (act) { g0 = s_g[htid*4]; g1 = s_g[htid*4+1]; g2 = s_g[htid*4+2]; g3 = s_g[htid*4+3]; }

    for (int cc = 0; cc < NCLS; cc += 2) {
        const int c = cc + cpar;
        float tmax = -1e30f, hmax = -1e30f;
        if (act) {
            float4 v = cls4[ibase + c * (HW / 4)];
            float b0 = bval(slog(v.x), g0);
            float b1 = bval(slog(v.y), g1);
            float b2 = bval(slog(v.z), g2);
            float b3 = bval(slog(v.w), g3);
            if (v.x > XC_TAG)  tmax = fmaxf(tmax, b0);
            if (v.y > XC_TAG)  tmax = fmaxf(tmax, b1);
            if (v.z > XC_TAG)  tmax = fmaxf(tmax, b2);
            if (v.w > XC_TAG)  tmax = fmaxf(tmax, b3);
            if (v.x > XC_HIST) hmax = fmaxf(hmax, b0);
            if (v.y > XC_HIST) hmax = fmaxf(hmax, b1);
            if (v.z > XC_HIST) hmax = fmaxf(hmax, b2);
            if (v.w > XC_HIST) hmax = fmaxf(hmax, b3);
        }
        tmax = fmaxf(tmax, __shfl_xor_sync(0xffffffffu, tmax, 1));
        tmax = fmaxf(tmax, __shfl_xor_sync(0xffffffffu, tmax, 2));
        tmax = fmaxf(tmax, __shfl_xor_sync(0xffffffffu, tmax, 4));
        hmax = fmaxf(hmax, __shfl_xor_sync(0xffffffffu, hmax, 1));
        hmax = fmaxf(hmax, __shfl_xor_sync(0xffffffffu, hmax, 2));
        hmax = fmaxf(hmax, __shfl_xor_sync(0xffffffffu, hmax, 4));
        if ((htid & 7) == 0 && lvalid) {
            int tb = (int)floorf(tmax);
            tb = max(0, min(255, tb));
            g_tag[tagbase + c * LINES_PAD] = (unsigned char)tb;
            if (hmax > -1e29f) {
                int hb = max(0, min(255, (int)floorf(hmax)));
                atomicAdd(&s_hist[hb], 1u);
            }
        }
    }
    __syncthreads();
    for (int i = tid; i < 256; i += 512) {
        uint32_t v = s_hist[i];
        if (v) atomicAdd(&g_hist[n][i], v);
    }
}

// ---------------------------------------------------------------------------
// cutoff: highest bin with >=1000 lines above, minus safety margin.
// Self-resets g_hist/g_cnt/g_lcnt for the next graph replay.
__global__ void k_cutoff() {
    int n = threadIdx.x;
    if (n >= NIMG) return;
    int cum[256];
    int acc = 0;
    for (int b = 255; b >= 0; --b) { acc += (int)g_hist[n][b]; cum[b] = acc; }
    int bcl = 0;
    for (int b = 255; b >= 0; --b) if (cum[b] >= TOPK) { bcl = b; break; }
    int m = bcl - BIN_MARGIN; if (m < 0) m = 0;
    while (m < bcl && 32 * cum[m] > CAND_CAP) ++m;   // capacity guard
    g_bcm[n] = m;
    for (int b = 0; b < 256; ++b) g_hist[n][b] = 0;
    g_cnt[n] = 0;
    g_lcnt[n] = 0;
}

// ---------------------------------------------------------------------------
// k_scan: compact hit-line slots into g_lines. Block-aggregated: one global
// atomic per block.
__global__ void __launch_bounds__(256) k_scan() {
    __shared__ int s_list[2048];
    __shared__ int s_n, s_base;
    const int n = blockIdx.y, tid = threadIdx.x;
    const int slot0 = blockIdx.x * 2048;            // 50 blocks x 2048 = 102400
    const int bcm = g_bcm[n];
    if (tid == 0) s_n = 0;
    __syncthreads();

    const unsigned char* tags = &g_tag[n * TAGS_PER_IMG];
    for (int i = tid; i < 2048; i += 256) {
        int slot = slot0 + i;
        int l32 = slot % LINES_PAD;
        if (l32 < LINES_PP && (int)tags[slot] >= bcm) {
            int p = atomicAdd(&s_n, 1);             // smem atomic (cheap, sparse)
            s_list[p] = slot;
        }
    }
    __syncthreads();
    const int cnt = s_n;
    if (tid == 0 && cnt > 0) s_base = atomicAdd(&g_lcnt[n], cnt);
    __syncthreads();
    if (cnt > 0) {
        int base = s_base;
        for (int i = tid; i < cnt; i += 256) {
            int pos = base + i;
            if (pos < LINE_CAP) g_lines[n][pos] = s_list[i];
        }
    }
}

// ---------------------------------------------------------------------------
// per-line candidate filter + warp-aggregated push into block stage buffer
__device__ __forceinline__ void line_proc(float x, float y, int hslot, int lane,
                                          float fb, unsigned long long* s_stage,
                                          int* s_cnt) {
    bool sel = false;
    unsigned key = 0, idx = 0;
    if (x > XC_TAG) {
        float b = bval(slog(x), slog(y));            // bit-identical to pass1
        if (b >= fb) {
            float p = sigm(x);                       // exact path for survivors
            if (p > 0.05f) {
                int c = hslot / LINES_PAD, l = hslot % LINES_PAD;
                float sc = __fmul_rn(p, sigm(y));
                key = __float_as_uint(sc);
                idx = (unsigned)((l * 32 + lane) * NCLS + c);
                sel = true;
            }
        }
    }
    unsigned m = __ballot_sync(0xffffffffu, sel);
    if (sel) {
        int leader = __ffs(m) - 1;
        int rank = __popc(m & ((1u << lane) - 1u));
        int basep = 0;
        if (lane == leader) basep = atomicAdd(s_cnt, __popc(m));   // smem atomic
        basep = __shfl_sync(m, basep, leader);
        s_stage[basep + rank] = ((unsigned long long)key << 32) | (unsigned)(~idx);
    }
}

// ---------------------------------------------------------------------------
// k_lines: block owns a contiguous 64-line chunk (<= 2048 candidates, provably
// fits stage). Line IDs prefetched to smem; each warp 8 lines, MLP=4 loads.
// No in-loop syncs; ONE flush (one global atomic) per block.
__global__ void __launch_bounds__(256) k_lines(const float* __restrict__ cls,
                                               const float* __restrict__ cent) {
    __shared__ unsigned long long s_stage[CHUNK * 32];
    __shared__ int s_lid[CHUNK];
    __shared__ int s_cnt, s_base;
    const int n = blockIdx.y, tid = threadIdx.x;
    const int lane = tid & 31, w = tid >> 5;
    const int lcnt = min(g_lcnt[n], LINE_CAP);
    const int c0 = blockIdx.x * CHUNK;
    if (c0 >= lcnt) return;
    const int nl = min(CHUNK, lcnt - c0);
    if (tid == 0) s_cnt = 0;
    if (tid < nl) s_lid[tid] = g_lines[n][c0 + tid];
    __syncthreads();
    const float fb = (float)g_bcm[n];

    for (int k = w; k < nl; k += 16) {          // 2 lines per iter (k, k+8)
        int k2 = k + 8;
        bool have2 = k2 < nl;
        int h1 = s_lid[k];
        int h2 = have2 ? s_lid[k2] : h1;
        int p1 = (h1 / LINES_PAD) * HW + (h1 % LINES_PAD) * 32 + lane;
        int p2 = (h2 / LINES_PAD) * HW + (h2 % LINES_PAD) * 32 + lane;
        // issue all four loads back-to-back (MLP=4)
        float x1 = cls[n * NCLS * HW + p1];
        float y1 = cent[n * HW + (h1 % LINES_PAD) * 32 + lane];
        float x2 = cls[n * NCLS * HW + p2];
        float y2 = cent[n * HW + (h2 % LINES_PAD) * 32 + lane];
        line_proc(x1, y1, h1, lane, fb, s_stage, &s_cnt);
        if (have2) line_proc(x2, y2, h2, lane, fb, s_stage, &s_cnt);
    }
    __syncthreads();
    // single flush
    const int cnt = s_cnt;
    if (tid == 0 && cnt > 0) s_base = atomicAdd(&g_cnt[n], cnt);
    __syncthreads();
    if (cnt > 0) {
        int base = s_base;
        for (int i = tid; i < cnt; i += 256) {
            int pos = base + i;
            if (pos < CAND_CAP) g_cand[n][pos] = s_stage[i];
        }
    }
}

// ---------------------------------------------------------------------------
// K4: exact top-1000 per image (maxkey-based fine hist -> refine -> bitonic),
// decode boxes
__global__ void __launch_bounds__(1024) k_select(const float* __restrict__ loc2,
                                                 const float* __restrict__ reg,
                                                 const int* __restrict__ isz) {
    __shared__ uint32_t s_hist[1024];
    __shared__ uint32_t s_cum[1024];
    __shared__ unsigned long long s_buf[4096];
    __shared__ unsigned s_wmax[32];
    __shared__ int s_cnt2, s_bf, s_rb;
    const int n = blockIdx.x, tid = threadIdx.x;
    const int Mn = min(g_cnt[n], CAND_CAP);

    s_hist[tid] = 0;
    if (tid == 0) { s_cnt2 = 0; s_bf = 0; }

    unsigned mk = 0;
    for (int i = tid; i < Mn; i += 1024) mk = max(mk, (unsigned)(g_cand[n][i] >> 32));
    for (int o = 16; o; o >>= 1) mk = max(mk, __shfl_xor_sync(0xffffffffu, mk, o));
    if ((tid & 31) == 0) s_wmax[tid >> 5] = mk;
    __syncthreads();
    if (tid == 0) {
        unsigned m2 = 0;
        for (int i = 0; i < 32; ++i) m2 = max(m2, s_wmax[i]);
        s_rb = (int)(m2 >> 17) - 1023;
    }
    __syncthreads();
    const int relbase = s_rb;

    for (int i = tid; i < Mn; i += 1024) {
        unsigned key = (unsigned)(g_cand[n][i] >> 32);
        int rel = (int)(key >> 17) - relbase;
        if (rel >= 0) atomicAdd(&s_hist[rel], 1u);
    }
    __syncthreads();

    s_cum[tid] = s_hist[tid];
    __syncthreads();
    for (int off = 1; off < 1024; off <<= 1) {
        uint32_t add = (tid + off < 1024) ? s_cum[tid + off] : 0u;
        __syncthreads();
        s_cum[tid] += add;
        __syncthreads();
    }
    const int total = (int)s_cum[0];
    const int target = min(TOPK, total);
    if (target > 0) {
        if ((int)s_cum[tid] >= target && (tid == 1023 || (int)s_cum[tid + 1] < target))
            s_bf = tid;
    }
    __syncthreads();
    const int bf = s_bf;

    for (int i = tid; i < Mn; i += 1024) {
        unsigned long long pk = g_cand[n][i];
        int rel = (int)((unsigned)(pk >> 32) >> 17) - relbase;
        if (rel >= bf) {
            int p = atomicAdd(&s_cnt2, 1);
            if (p < 4096) s_buf[p] = pk;
        }
    }
    __syncthreads();
    const int cnt2 = min(s_cnt2, 4096);
    const int N2 = (cnt2 <= 1024) ? 1024 : ((cnt2 <= 2048) ? 2048 : 4096);
    for (int i = tid; i < N2; i += 1024)
        if (i >= cnt2) s_buf[i] = 0ull;
    __syncthreads();

    for (int k = 2; k <= N2; k <<= 1) {
        for (int j = k >> 1; j > 0; j >>= 1) {
            for (int t = tid; t < N2; t += 1024) {
                int ixj = t ^ j;
                if (ixj > t) {
                    unsigned long long a = s_buf[t], b = s_buf[ixj];
                    bool up = (t & k) == 0;
                    if (up ? (a < b) : (a > b)) { s_buf[t] = b; s_buf[ixj] = a; }
                }
            }
            __syncthreads();
        }
    }

    if (tid < TOPK) {
        unsigned long long pk = (tid < cnt2) ? s_buf[tid] : 0ull;
        unsigned key = (unsigned)(pk >> 32);
        if (key == 0u) {
            g_score[n][tid] = 0.0f;
            g_label[n][tid] = 0;
            g_box[n][tid]  = make_float4(0.f, 0.f, 0.f, 0.f);
            g_obox[n][tid] = make_float4(0.f, 0.f, 0.f, 0.f);
        } else {
            unsigned idx = ~(unsigned)(pk & 0xffffffffull);
            int l = (int)(idx / NCLS), c = (int)(idx % NCLS);
            float sc = __uint_as_float(key);
            float lx = loc2[2 * l], ly = loc2[2 * l + 1];
            const float* rg = reg + (long long)n * 4 * HW;
            float r0 = rg[l], r1 = rg[HW + l], r2 = rg[2 * HW + l], r3 = rg[3 * HW + l];
            float ym = __fsub_rn((float)isz[2 * n],     1.0f);
            float xm = __fsub_rn((float)isz[2 * n + 1], 1.0f);
            float x1 = fminf(fmaxf(__fsub_rn(lx, r0), 0.0f), xm);
            float y1 = fminf(fmaxf(__fsub_rn(ly, r1), 0.0f), ym);
            float x2 = fminf(fmaxf(__fadd_rn(lx, r2), 0.0f), xm);
            float y2 = fminf(fmaxf(__fadd_rn(ly, r3), 0.0f), ym);
            int label = c + 1;
            float off = __fmul_rn((float)label, 100000.0f);
            g_score[n][tid] = sc;
            g_label[n][tid] = label;
            g_box[n][tid]  = make_float4(x1, y1, x2, y2);
            g_obox[n][tid] = make_float4(__fadd_rn(x1, off), __fadd_rn(y1, off),
                                         __fadd_rn(x2, off), __fadd_rn(y2, off));
        }
    }
}

// ---------------------------------------------------------------------------
// K5: per-class greedy NMS + keep prefix-scan + top-100 output
__global__ void __launch_bounds__(1024) k_nms_out(float* __restrict__ out) {
    __shared__ float4         s_ob[TOPK];
    __shared__ float          s_area[TOPK];
    __shared__ unsigned char  s_lab[TOPK];
    __shared__ unsigned char  s_supp[TOPK];
    __shared__ unsigned short s_pool[TOPK];
    __shared__ int            s_count[NCLS];
    __shared__ int            s_off[NCLS + 1];
    __shared__ int            s_scan[1024];

    const int n = blockIdx.x, tid = threadIdx.x, lane = tid & 31, w = tid >> 5;

    if (tid < NCLS) s_count[tid] = 0;
    if (tid < TOPK) {
        float4 b = g_obox[n][tid];
        s_ob[tid] = b;
        s_area[tid] = __fmul_rn(__fadd_rn(__fsub_rn(b.z, b.x), 1.0f),
                                __fadd_rn(__fsub_rn(b.w, b.y), 1.0f));
        int L = g_label[n][tid];
        s_lab[tid] = (unsigned char)L;
        s_supp[tid] = 0;
        if (L > 0) atomicAdd(&s_count[L - 1], 1);
    }
    __syncthreads();
    if (tid == 0) {
        int a = 0;
        for (int c = 0; c < NCLS; ++c) { s_off[c] = a; a += s_count[c]; }
        s_off[NCLS] = a;
    }
    __syncthreads();

    for (int c = w; c < NCLS; c += 32) {
        int off = s_off[c], cnt = 0;
        unsigned char want = (unsigned char)(c + 1);
        for (int base = 0; base < TOPK; base += 32) {
            int r = base + lane;
            bool hit = (r < TOPK) && (s_lab[r] == want);
            unsigned m = __ballot_sync(0xffffffffu, hit);
            if (hit) s_pool[off + cnt + __popc(m & ((1u << lane) - 1u))] = (unsigned short)r;
            cnt += __popc(m);
        }
    }
    __syncthreads();

    for (int c = w; c < NCLS; c += 32) {
        int off = s_off[c], m = s_count[c];
        for (int i = 0; i < m; ++i) {
            __syncwarp();
            int ri = s_pool[off + i];
            if (s_supp[ri]) continue;
            float4 bi = s_ob[ri];
            float  ai = s_area[ri];
            for (int j = i + 1 + lane; j < m; j += 32) {
                int rj = s_pool[off + j];
                float4 bj = s_ob[rj];
                float ww = __fadd_rn(__fsub_rn(fminf(bi.z, bj.z), fmaxf(bi.x, bj.x)), 1.0f);
                float hh = __fadd_rn(__fsub_rn(fminf(bi.w, bj.w), fmaxf(bi.y, bj.y)), 1.0f);
                ww = fmaxf(ww, 0.0f); hh = fmaxf(hh, 0.0f);
                float inter = __fmul_rn(ww, hh);
                float uni = __fsub_rn(__fadd_rn(ai, s_area[rj]), inter);
                float iou = __fdiv_rn(inter, uni);
                if (iou > 0.6f) s_supp[rj] = 1;
            }
        }
        __syncwarp();
    }
    __syncthreads();

    int keep = (tid < TOPK && s_lab[tid] > 0 && !s_supp[tid]) ? 1 : 0;
    s_scan[tid] = keep;
    __syncthreads();
    for (int off = 1; off < 1024; off <<= 1) {
        int v = (tid >= off) ? s_scan[tid - off] : 0;
        __syncthreads();
        s_scan[tid] += v;
        __syncthreads();
    }

    for (int i = tid; i < OUTK * 6; i += 1024) out[n * OUTK * 6 + i] = 0.0f;
    __syncthreads();

    if (keep) {
        int pos = s_scan[tid] - 1;
        if (pos < OUTK) {
            float4 b = g_box[n][tid];
            float* o = out + n * OUTK * 6 + pos * 6;
            o[0] = b.x; o[1] = b.y; o[2] = b.z; o[3] = b.w;
            o[4] = sqrtf(g_score[n][tid]);
            o[5] = (float)g_label[n][tid];
        }
    }
}

// ---------------------------------------------------------------------------
extern "C" void kernel_launch(void* const* d_in, const int* in_sizes, int n_in,
                              void* d_out, int out_size) {
    const float* locations = (const float*)d_in[0];
    const float* box_cls   = (const float*)d_in[1];
    const float* box_reg   = (const float*)d_in[2];
    const float* cent      = (const float*)d_in[3];
    const int*   isz       = (const int*)d_in[4];
    float* out = (float*)d_out;

    k_pass1<<<dim3(40, NIMG), 512>>>(box_cls, cent);
    k_cutoff<<<1, 32>>>();
    k_scan<<<dim3(50, NIMG), 256>>>();
    k_lines<<<dim3(LINE_CAP / CHUNK, NIMG), 256>>>(box_cls, cent);
    k_select<<<NIMG, 1024>>>(locations, box_reg, isz);
    k_nms_out<<<NIMG, 1024>>>(out);
}